// round 1
// baseline (speedup 1.0000x reference)
#include <cuda_runtime.h>
#include <cuda_bf16.h>
#include <cstdint>

#define DIM 64
#define NCI_MAX 150000
#define FMA_MAX 100000
#define GATHER_BLOCKS 2048
#define GATHER_TPB 256

// ---------------- scratch (device globals: allocation-free rule) ----------------
__device__ __align__(128) __nv_bfloat16 g_Hn[NCI_MAX * DIM];   // 19.2 MB
__device__ __align__(128) __nv_bfloat16 g_Hm[NCI_MAX * DIM];   // 19.2 MB
__device__ __align__(128) __nv_bfloat16 g_Fb[FMA_MAX * DIM];   // 12.8 MB
__device__ float g_part[GATHER_BLOCKS];

// ---------------- packed f32x2 helpers ----------------
__device__ __forceinline__ unsigned long long pack2(float lo, float hi) {
    unsigned long long r;
    asm("mov.b64 %0, {%1, %2};" : "=l"(r) : "f"(lo), "f"(hi));
    return r;
}
__device__ __forceinline__ void unpack2(unsigned long long v, float& lo, float& hi) {
    asm("mov.b64 {%0, %1}, %2;" : "=f"(lo), "=f"(hi) : "l"(v));
}
__device__ __forceinline__ unsigned long long ffma2(unsigned long long a,
                                                    unsigned long long b,
                                                    unsigned long long c) {
    unsigned long long d;
    asm("fma.rn.f32x2 %0, %1, %2, %3;" : "=l"(d) : "l"(a), "l"(b), "l"(c));
    return d;
}

// exact bf16 -> f32 (bf16 is the top half of f32): pure ALU-pipe, no CVT
__device__ __forceinline__ float2 b2f(unsigned u) {
    return make_float2(__uint_as_float(u << 16), __uint_as_float(u & 0xffff0000u));
}

// ---------------- kernel 1: Hn/Hm precompute ----------------
// Block: 128 threads = (tx:8 col-groups, ty:16 row-groups). Tile: 64 rows.
// Thread tile: 4 rows x 8 cols, f32x2 accumulator lanes = {Hn, Hm}.
// Shared: sM[c][j] = {Mn[c][j], Mm[c][j]} padded to 65 float2/row,
//         sE[r][j] padded to 65 floats/row. Both conflict-free for this pattern.
__global__ __launch_bounds__(128) void precompute_h(
    const float* __restrict__ nci,
    const float* __restrict__ Mn,
    const float* __restrict__ Mm,
    int nrows)
{
    extern __shared__ unsigned char smem[];
    float2 (*sM)[DIM + 1] = reinterpret_cast<float2(*)[DIM + 1]>(smem);
    float  (*sE)[DIM + 1] = reinterpret_cast<float(*)[DIM + 1]>(
        smem + sizeof(float2) * DIM * (DIM + 1));

    const int tid = threadIdx.x;
    const int tx = tid & 7;          // col group
    const int ty = tid >> 3;         // row group (0..15)
    const int rowBase = blockIdx.x * 64;

    for (int idx = tid; idx < DIM * DIM; idx += 128) {
        int c = idx >> 6, j = idx & 63;
        sM[c][j] = make_float2(Mn[idx], Mm[idx]);
    }
    for (int idx = tid; idx < DIM * DIM; idx += 128) {
        int r = idx >> 6, j = idx & 63;
        int gr = rowBase + r;
        sE[r][j] = (gr < nrows) ? nci[(size_t)gr * DIM + j] : 0.0f;
    }
    __syncthreads();

    unsigned long long acc[8][4];
#pragma unroll
    for (int cc = 0; cc < 8; cc++)
#pragma unroll
        for (int rr = 0; rr < 4; rr++) acc[cc][rr] = 0ull;

#pragma unroll 4
    for (int j = 0; j < DIM; j++) {
        unsigned long long e2[4];
#pragma unroll
        for (int rr = 0; rr < 4; rr++) {
            float e = sE[ty * 4 + rr][j];
            e2[rr] = pack2(e, e);
        }
#pragma unroll
        for (int cc = 0; cc < 8; cc++) {
            float2 m = sM[tx + cc * 8][j];
            unsigned long long m2;
            asm("mov.b64 %0, {%1, %2};" : "=l"(m2) : "f"(m.x), "f"(m.y));
#pragma unroll
            for (int rr = 0; rr < 4; rr++)
                acc[cc][rr] = ffma2(m2, e2[rr], acc[cc][rr]);
        }
    }

#pragma unroll
    for (int rr = 0; rr < 4; rr++) {
        int r = rowBase + ty * 4 + rr;
        if (r < nrows) {
#pragma unroll
            for (int cc = 0; cc < 8; cc++) {
                int c = tx + cc * 8;
                float hn, hm;
                unpack2(acc[cc][rr], hn, hm);
                g_Hn[(size_t)r * DIM + c] = __float2bfloat16(hn);
                g_Hm[(size_t)r * DIM + c] = __float2bfloat16(hm);
            }
        }
    }
}

// ---------------- kernel 2: F -> bf16 ----------------
__global__ void convert_f(const float* __restrict__ f, int nelem)
{
    int stride = gridDim.x * blockDim.x;
    int nv = nelem >> 2;
    for (int k = blockIdx.x * blockDim.x + threadIdx.x; k < nv; k += stride) {
        float4 v = reinterpret_cast<const float4*>(f)[k];
        __nv_bfloat162* o = reinterpret_cast<__nv_bfloat162*>(g_Fb) + (size_t)k * 2;
        o[0] = __floats2bfloat162_rn(v.x, v.y);
        o[1] = __floats2bfloat162_rn(v.z, v.w);
    }
}

// ---------------- kernel 3: gather + squared-diff partial sums ----------------
__global__ __launch_bounds__(GATHER_TPB) void gather_loss(
    const int* __restrict__ pos_n,
    const int* __restrict__ pos_m,
    const int* __restrict__ pos_f,
    int B)
{
    float acc = 0.0f;
    const int stride = gridDim.x * blockDim.x;
    for (int i = blockIdx.x * blockDim.x + threadIdx.x; i < B; i += stride) {
        const uint4* hn = reinterpret_cast<const uint4*>(g_Hn + (size_t)pos_n[i] * DIM);
        const uint4* hm = reinterpret_cast<const uint4*>(g_Hm + (size_t)pos_m[i] * DIM);
        const uint4* fb = reinterpret_cast<const uint4*>(g_Fb + (size_t)pos_f[i] * DIM);
#pragma unroll
        for (int k = 0; k < 8; k++) {
            uint4 a = hn[k];
            uint4 b = hm[k];
            uint4 c = fb[k];
            unsigned aw[4] = {a.x, a.y, a.z, a.w};
            unsigned bw[4] = {b.x, b.y, b.z, b.w};
            unsigned cw[4] = {c.x, c.y, c.z, c.w};
#pragma unroll
            for (int w = 0; w < 4; w++) {
                float2 ha = b2f(aw[w]);
                float2 hb = b2f(bw[w]);
                float2 hf = b2f(cw[w]);
                float d0 = ha.x - hf.x; acc = fmaf(d0, d0, acc);
                float d1 = ha.y - hf.y; acc = fmaf(d1, d1, acc);
                float d2 = hb.x - hf.x; acc = fmaf(d2, d2, acc);
                float d3 = hb.y - hf.y; acc = fmaf(d3, d3, acc);
            }
        }
    }

    // warp reduce
#pragma unroll
    for (int off = 16; off > 0; off >>= 1)
        acc += __shfl_xor_sync(0xffffffffu, acc, off);

    __shared__ float ws[GATHER_TPB / 32];
    int lane = threadIdx.x & 31;
    int wid = threadIdx.x >> 5;
    if (lane == 0) ws[wid] = acc;
    __syncthreads();
    if (wid == 0) {
        float v = (lane < GATHER_TPB / 32) ? ws[lane] : 0.0f;
#pragma unroll
        for (int off = 4; off > 0; off >>= 1)
            v += __shfl_xor_sync(0xffffffffu, v, off);
        if (lane == 0) g_part[blockIdx.x] = v;
    }
}

// ---------------- kernel 4: deterministic final reduce ----------------
__global__ void final_reduce(float* __restrict__ out, int nparts)
{
    __shared__ float s[256];
    float a = 0.0f;
    for (int i = threadIdx.x; i < nparts; i += 256) a += g_part[i];
    s[threadIdx.x] = a;
    __syncthreads();
    for (int off = 128; off > 0; off >>= 1) {
        if (threadIdx.x < off) s[threadIdx.x] += s[threadIdx.x + off];
        __syncthreads();
    }
    if (threadIdx.x == 0) out[0] = s[0];
}

// ---------------- launch ----------------
extern "C" void kernel_launch(void* const* d_in, const int* in_sizes, int n_in,
                              void* d_out, int out_size)
{
    const int*   pos_n = (const int*)d_in[0];
    const int*   pos_m = (const int*)d_in[1];
    const int*   pos_f = (const int*)d_in[2];
    const float* nci   = (const float*)d_in[3];
    const float* fmae  = (const float*)d_in[4];
    const float* Mn    = (const float*)d_in[5];
    const float* Mm    = (const float*)d_in[6];

    int B = in_sizes[0];
    int nci_rows = in_sizes[3] / DIM;
    if (nci_rows > NCI_MAX) nci_rows = NCI_MAX;
    int f_elems = in_sizes[4];
    if (f_elems > FMA_MAX * DIM) f_elems = FMA_MAX * DIM;

    const int smem_bytes = (int)(sizeof(float2) * DIM * (DIM + 1) +
                                 sizeof(float)  * DIM * (DIM + 1));   // ~49.9 KB
    static bool attr_set = false;
    if (!attr_set) {
        cudaFuncSetAttribute(precompute_h,
                             cudaFuncAttributeMaxDynamicSharedMemorySize, smem_bytes);
        attr_set = true;
    }

    int hBlocks = (nci_rows + 63) / 64;
    precompute_h<<<hBlocks, 128, smem_bytes>>>(nci, Mn, Mm, nci_rows);
    convert_f<<<512, 256>>>(fmae, f_elems);
    gather_loss<<<GATHER_BLOCKS, GATHER_TPB>>>(pos_n, pos_m, pos_f, B);
    final_reduce<<<1, 256>>>((float*)d_out, GATHER_BLOCKS);
}